// round 14
// baseline (speedup 1.0000x reference)
#include <cuda_runtime.h>
#include <cuda_fp16.h>
#include <math.h>
#include <stdint.h>

#define L_ 4
#define B_ 4
#define T_ 2048
#define C_ 1024
#define F_ 4096
#define BT_ (B_*T_)
#define NCH 16
#define CHUNK (T_/NCH)     // 128
#define NBC (B_*NCH*C_)    // 65536

// ---------------- scratch (device globals: no allocations allowed) ----------
__device__ float  g_h   [BT_ * C_];
__device__ float  g_k   [BT_ * C_];
__device__ float  g_v   [BT_ * C_];
__device__ float  g_sr  [BT_ * C_];
__device__ float  g_cs  [6 * NBC];
__device__ __half g_xk  [BT_ * C_];
__device__ __half g_xv  [BT_ * C_];
__device__ __half g_xr  [BT_ * C_];
__device__ __half g_rwkv[BT_ * C_];
__device__ __half g_kf  [BT_ * F_];
#define WPL (5*C_*C_ + 2*C_*F_)
__device__ __half g_wh  [L_ * WPL];

// ---------------- fused weight pre-conversion to fp16 (ONE launch) ----------
struct SrcPtrs { const float* p[7]; };

// float4 segment sizes: 5 CC groups of Q, 2 FC groups of QF
#define QCC ((size_t)L_*C_*C_/4)
#define QFC ((size_t)L_*F_*C_/4)
#define N4TOT (5*QCC + 2*QFC)

__global__ __launch_bounds__(256) void cvtw_all(SrcPtrs sp, __half* __restrict__ dst)
{
    size_t i = (size_t)blockIdx.x * 256 + threadIdx.x;
    if (i >= N4TOT) return;
    int seg; size_t off;
    if (i < 5 * QCC)            { seg = (int)(i / QCC);  off = i - seg * QCC; }
    else if (i < 5 * QCC + QFC) { seg = 5;               off = i - 5 * QCC; }
    else                        { seg = 6;               off = i - 5 * QCC - QFC; }
    float4 v = ((const float4*)sp.p[seg])[off];
    __half2 h01 = __floats2half2_rn(v.x, v.y);
    __half2 h23 = __floats2half2_rn(v.z, v.w);
    ((__half2*)dst)[2 * i]     = h01;
    ((__half2*)dst)[2 * i + 1] = h23;
}

// ---------------- layernorm ----------------------------------------
__global__ __launch_bounds__(256) void ln_kernel(
    const float* __restrict__ x, const float* __restrict__ w,
    const float* __restrict__ b, float* __restrict__ y)
{
    int row = blockIdx.x;
    const float* xr = x + (size_t)row * C_;
    float*       yr = y + (size_t)row * C_;

    float s = 0.f, s2 = 0.f;
    for (int i = threadIdx.x; i < C_; i += 256) {
        float t = xr[i];
        s += t;
        s2 = fmaf(t, t, s2);
    }
    #pragma unroll
    for (int o = 16; o > 0; o >>= 1) {
        s  += __shfl_xor_sync(0xffffffffu, s,  o);
        s2 += __shfl_xor_sync(0xffffffffu, s2, o);
    }
    __shared__ float sh[2][8];
    int wid = threadIdx.x >> 5;
    if ((threadIdx.x & 31) == 0) { sh[0][wid] = s; sh[1][wid] = s2; }
    __syncthreads();
    if (threadIdx.x < 32) {
        float a  = (threadIdx.x < 8) ? sh[0][threadIdx.x] : 0.f;
        float c2 = (threadIdx.x < 8) ? sh[1][threadIdx.x] : 0.f;
        #pragma unroll
        for (int o = 4; o > 0; o >>= 1) {
            a  += __shfl_xor_sync(0xffffffffu, a,  o);
            c2 += __shfl_xor_sync(0xffffffffu, c2, o);
        }
        if (threadIdx.x == 0) { sh[0][0] = a; sh[1][0] = c2; }
    }
    __syncthreads();
    float mean = sh[0][0] * (1.f / C_);
    float var  = sh[1][0] * (1.f / C_) - mean * mean;
    float rstd = rsqrtf(var + 1e-5f);
    for (int i = threadIdx.x; i < C_; i += 256)
        yr[i] = (xr[i] - mean) * rstd * w[i] + b[i];
}

// ---------------- time-shift mixes (fp16 outputs: GEMM A operands) ----------
__global__ __launch_bounds__(256) void mix3_kernel(
    const float* __restrict__ h,
    const float* __restrict__ mk, const float* __restrict__ mv,
    const float* __restrict__ mr,
    __half* __restrict__ xk, __half* __restrict__ xv, __half* __restrict__ xr)
{
    int i = blockIdx.x * 256 + threadIdx.x;
    int c = i & (C_ - 1);
    int t = (i >> 10) & (T_ - 1);
    float hv = h[i];
    float hh = (t == 0) ? 0.f : h[i - C_];
    float a = mk[c], bv = mv[c], r = mr[c];
    xk[i] = __float2half(hv * a  + hh * (1.f - a));
    xv[i] = __float2half(hv * bv + hh * (1.f - bv));
    xr[i] = __float2half(hv * r  + hh * (1.f - r));
}

__global__ __launch_bounds__(256) void mix2_kernel(
    const float* __restrict__ h,
    const float* __restrict__ mk, const float* __restrict__ mr,
    __half* __restrict__ xk, __half* __restrict__ xr)
{
    int i = blockIdx.x * 256 + threadIdx.x;
    int c = i & (C_ - 1);
    int t = (i >> 10) & (T_ - 1);
    float hv = h[i];
    float hh = (t == 0) ? 0.f : h[i - C_];
    float a = mk[c], r = mr[c];
    xk[i] = __float2half(hv * a + hh * (1.f - a));
    xr[i] = __float2half(hv * r + hh * (1.f - r));
}

// ---------------- WKV: chunked parallel scan --------------------------------
__global__ __launch_bounds__(256) void wkv_pass1(
    const float* __restrict__ k, const float* __restrict__ v,
    const float* __restrict__ td,
    float* __restrict__ sLa, float* __restrict__ sLb, float* __restrict__ sLp)
{
    int idx = blockIdx.x * 256 + threadIdx.x;
    int c  = idx & (C_ - 1);
    int ch = (idx >> 10) & (NCH - 1);
    int b  = idx >> 14;
    float w = -__expf(td[c]);
    float aa = 0.f, bb = 0.f, pp = -1e38f;
    size_t base = ((size_t)b * T_ + (size_t)ch * CHUNK) * C_ + c;
    #pragma unroll 4
    for (int i = 0; i < CHUNK; i++) {
        float kk = k[base + (size_t)i * C_];
        float vv = v[base + (size_t)i * C_];
        float ww2 = pp + w;
        float qq2 = fmaxf(ww2, kk);
        float e1 = __expf(ww2 - qq2);
        float e2 = __expf(kk  - qq2);
        aa = e1 * aa + e2 * vv;
        bb = e1 * bb + e2;
        pp = qq2;
    }
    sLa[idx] = aa; sLb[idx] = bb; sLp[idx] = pp;
}

__global__ __launch_bounds__(256) void wkv_combine(
    const float* __restrict__ sLa, const float* __restrict__ sLb,
    const float* __restrict__ sLp,
    float* __restrict__ pA, float* __restrict__ pB, float* __restrict__ pP,
    const float* __restrict__ td)
{
    int idx = blockIdx.x * 256 + threadIdx.x;
    int c = idx & (C_ - 1);
    int b = idx >> 10;
    float w  = -__expf(td[c]);
    float wc = w * (float)CHUNK;
    float aa = 0.f, bb = 0.f, pp = -1e38f;
    int base = b * NCH * C_ + c;
    #pragma unroll
    for (int ch = 0; ch < NCH; ch++) {
        int j = base + ch * C_;
        pA[j] = aa; pB[j] = bb; pP[j] = pp;
        float adv = pp + wc;
        float la = sLa[j], lb = sLb[j], lp = sLp[j];
        float q  = fmaxf(adv, lp);
        float e1 = __expf(adv - q);
        float e2 = __expf(lp  - q);
        aa = e1 * aa + e2 * la;
        bb = e1 * bb + e2 * lb;
        pp = q;
    }
}

__global__ __launch_bounds__(256) void wkv_pass2(
    const float* __restrict__ k, const float* __restrict__ v,
    const float* __restrict__ sr, __half* __restrict__ out,
    const float* __restrict__ td, const float* __restrict__ tf,
    const float* __restrict__ pA, const float* __restrict__ pB,
    const float* __restrict__ pP)
{
    int idx = blockIdx.x * 256 + threadIdx.x;
    int c  = idx & (C_ - 1);
    int ch = (idx >> 10) & (NCH - 1);
    int b  = idx >> 14;
    float w = -__expf(td[c]);
    float u = tf[c];
    float aa = pA[idx], bb = pB[idx], pp = pP[idx];
    size_t base = ((size_t)b * T_ + (size_t)ch * CHUNK) * C_ + c;
    #pragma unroll 4
    for (int i = 0; i < CHUNK; i++) {
        size_t off = base + (size_t)i * C_;
        float kk = k[off];
        float vv = v[off];
        float ww = u + kk;
        float qq = fmaxf(pp, ww);
        float e1 = __expf(pp - qq);
        float e2 = __expf(ww - qq);
        out[off] = __float2half(sr[off] * ((e1 * aa + e2 * vv) / (e1 * bb + e2)));
        float ww2 = pp + w;
        float qq2 = fmaxf(ww2, kk);
        float e1b = __expf(ww2 - qq2);
        float e2b = __expf(kk  - qq2);
        aa = e1b * aa + e2b * vv;
        bb = e1b * bb + e2b;
        pp = qq2;
    }
}

// ---------------- fp16 mma.sync GEMM: Y = X[M,K] . W[N,K]^T -----------------
// 128x128 CTA tile, 8 warps (2x4 grid, 64x32 warp tiles), BK=32,
// m16n8k16, scalar LDS fragment loads (R12-proven), 4-stage cp.async.
#define BM 128
#define BN 128
#define BK 32
#define SH 40                          // smem halves per row (conflict-free)
#define NSTAGE 4
#define STGH ((BM+BN)*SH)              // halves per stage
#define SMEM_BYTES (NSTAGE*STGH*2)

__device__ __forceinline__ void cp16(unsigned smaddr, const __half* g) {
    asm volatile("cp.async.cg.shared.global [%0], [%1], 16;" :: "r"(smaddr), "l"(g));
}

template<int EPI, int ACCUM, int OUTH>
__global__ __launch_bounds__(256, 2) void gemm_fp16(
    const __half* __restrict__ X, const __half* __restrict__ W,
    void* __restrict__ Yv, const float* __restrict__ mul,
    int M, int N, int K)
{
    extern __shared__ __half sm[];

    int tid  = threadIdx.x;
    int warp = tid >> 5, lane = tid & 31;
    int wm = warp >> 2, wn = warp & 3;          // 2 x 4 warp grid, 64x32 tiles
    int gid = lane >> 2, tig = lane & 3;

    const int bMr = blockIdx.y * BM, bNr = blockIdx.x * BN;
    // loader: row r = tid>>1 covers A row r and B row r; two 16B chunks each
    int r  = tid >> 1;
    int c0 = tid & 1;                           // chunks c0 and c0+2 (of 4)
    const __half* GA = X + (size_t)(bMr + r) * K;
    const __half* GB = W + (size_t)(bNr + r) * K;
    unsigned sbase = (unsigned)__cvta_generic_to_shared(sm);
    unsigned rowA = (unsigned)(r * SH) * 2u;            // byte offset of A row
    unsigned rowB = (unsigned)((BM + r) * SH) * 2u;     // byte offset of B row

    float acc[4][4][4];
    #pragma unroll
    for (int i = 0; i < 4; i++)
        #pragma unroll
        for (int j = 0; j < 4; j++)
            #pragma unroll
            for (int q = 0; q < 4; q++) acc[i][j][q] = 0.f;

    int niter = K / BK;

    #pragma unroll
    for (int s = 0; s < NSTAGE - 1; s++) {
        unsigned dst = sbase + (unsigned)(s * STGH) * 2u;
        int k0 = s * BK;
        #pragma unroll
        for (int cc = 0; cc < 2; cc++) {
            int ch = c0 + cc * 2;               // chunk index 0..3
            cp16(dst + rowA + ch * 16u, GA + k0 + ch * 8);
            cp16(dst + rowB + ch * 16u, GB + k0 + ch * 8);
        }
        asm volatile("cp.async.commit_group;" ::: "memory");
    }

    for (int kt = 0; kt < niter; kt++) {
        asm volatile("cp.async.wait_group 2;" ::: "memory");
        __syncthreads();

        int nx = kt + NSTAGE - 1;
        if (nx < niter) {
            unsigned dst = sbase + (unsigned)((nx % NSTAGE) * STGH) * 2u;
            int k0 = nx * BK;
            #pragma unroll
            for (int cc = 0; cc < 2; cc++) {
                int ch = c0 + cc * 2;
                cp16(dst + rowA + ch * 16u, GA + k0 + ch * 8);
                cp16(dst + rowB + ch * 16u, GB + k0 + ch * 8);
            }
        }
        asm volatile("cp.async.commit_group;" ::: "memory");

        const __half* Ab = sm + (kt % NSTAGE) * STGH;
        const __half* Bb = Ab + BM * SH;

        #pragma unroll
        for (int kk = 0; kk < 2; kk++) {        // two K=16 slices per BK=32
            int k0 = kk * 16;
            unsigned af[4][4], bf[4][2];
            #pragma unroll
            for (int i = 0; i < 4; i++) {
                int rb = wm * 64 + i * 16 + gid;
                const __half* p0 = Ab + rb * SH + k0 + 2 * tig;
                const __half* p1 = Ab + (rb + 8) * SH + k0 + 2 * tig;
                af[i][0] = *(const unsigned*)(p0);
                af[i][1] = *(const unsigned*)(p1);
                af[i][2] = *(const unsigned*)(p0 + 8);
                af[i][3] = *(const unsigned*)(p1 + 8);
            }
            #pragma unroll
            for (int j = 0; j < 4; j++) {
                int nb = wn * 32 + j * 8 + gid;
                const __half* p = Bb + nb * SH + k0 + 2 * tig;
                bf[j][0] = *(const unsigned*)(p);
                bf[j][1] = *(const unsigned*)(p + 8);
            }
            #pragma unroll
            for (int i = 0; i < 4; i++)
                #pragma unroll
                for (int j = 0; j < 4; j++)
                    asm volatile(
                        "mma.sync.aligned.m16n8k16.row.col.f32.f16.f16.f32 "
                        "{%0,%1,%2,%3}, {%4,%5,%6,%7}, {%8,%9}, {%0,%1,%2,%3};"
                        : "+f"(acc[i][j][0]), "+f"(acc[i][j][1]),
                          "+f"(acc[i][j][2]), "+f"(acc[i][j][3])
                        : "r"(af[i][0]), "r"(af[i][1]), "r"(af[i][2]), "r"(af[i][3]),
                          "r"(bf[j][0]), "r"(bf[j][1]));
        }
    }

    float*  Yf = (float*)Yv;
    __half* Yh = (__half*)Yv;
    #pragma unroll
    for (int i = 0; i < 4; i++) {
        int rg = bMr + wm * 64 + i * 16 + gid;
        #pragma unroll
        for (int j = 0; j < 4; j++) {
            int cg = bNr + wn * 32 + j * 8 + tig * 2;
            #pragma unroll
            for (int h = 0; h < 2; h++) {
                int rr = rg + h * 8;
                #pragma unroll
                for (int q = 0; q < 2; q++) {
                    float v = acc[i][j][h * 2 + q];
                    if (EPI == 1) v = 1.f / (1.f + __expf(-v));
                    if (EPI == 2) { v = fmaxf(v, 0.f); v = v * v; }
                    size_t idx = (size_t)rr * N + (cg + q);
                    if (ACCUM) {
                        float m = mul ? mul[idx] : 1.f;
                        Yf[idx] += m * v;
                    } else if (OUTH) {
                        Yh[idx] = __float2half(v);
                    } else {
                        Yf[idx] = v;
                    }
                }
            }
        }
    }
}

// ---------------- host orchestration ----------------------------------------
extern "C" void kernel_launch(void* const* d_in, const int* in_sizes, int n_in,
                              void* d_out, int out_size)
{
    const float* x    = (const float*)d_in[0];
    const float* ln0w = (const float*)d_in[1];
    const float* ln0b = (const float*)d_in[2];
    const float* ln1w = (const float*)d_in[3];
    const float* ln1b = (const float*)d_in[4];
    const float* ln2w = (const float*)d_in[5];
    const float* ln2b = (const float*)d_in[6];
    const float* td   = (const float*)d_in[7];
    const float* tf   = (const float*)d_in[8];
    const float* tmk  = (const float*)d_in[9];
    const float* tmv  = (const float*)d_in[10];
    const float* tmr  = (const float*)d_in[11];
    const float* Wk   = (const float*)d_in[12];
    const float* Wv   = (const float*)d_in[13];
    const float* Wr   = (const float*)d_in[14];
    const float* Wo   = (const float*)d_in[15];
    const float* cmk  = (const float*)d_in[16];
    const float* cmr  = (const float*)d_in[17];
    const float* Wck  = (const float*)d_in[18];
    const float* Wcv  = (const float*)d_in[19];
    const float* Wcr  = (const float*)d_in[20];

    float* xb = (float*)d_out;

    float  *h, *kb, *vb, *srb, *cs;
    __half *xk, *xv, *xr, *rwkvb, *kfb, *whb;
    cudaGetSymbolAddress((void**)&h,     g_h);
    cudaGetSymbolAddress((void**)&kb,    g_k);
    cudaGetSymbolAddress((void**)&vb,    g_v);
    cudaGetSymbolAddress((void**)&srb,   g_sr);
    cudaGetSymbolAddress((void**)&cs,    g_cs);
    cudaGetSymbolAddress((void**)&xk,    g_xk);
    cudaGetSymbolAddress((void**)&xv,    g_xv);
    cudaGetSymbolAddress((void**)&xr,    g_xr);
    cudaGetSymbolAddress((void**)&rwkvb, g_rwkv);
    cudaGetSymbolAddress((void**)&kfb,   g_kf);
    cudaGetSymbolAddress((void**)&whb,   g_wh);

    float* sLa = cs;
    float* sLb = cs + NBC;
    float* sLp = cs + 2 * NBC;
    float* pA  = cs + 3 * NBC;
    float* pB  = cs + 4 * NBC;
    float* pP  = cs + 5 * NBC;

    size_t nCC = (size_t)L_ * C_ * C_;
    size_t nFC = (size_t)L_ * F_ * C_;
    __half* tWk  = whb;
    __half* tWv  = tWk  + nCC;
    __half* tWr  = tWv  + nCC;
    __half* tWo  = tWr  + nCC;
    __half* tWcr = tWo  + nCC;
    __half* tWck = tWcr + nCC;
    __half* tWcv = tWck + nFC;

    // ONE fused conversion launch (order matches g_wh segment layout)
    {
        SrcPtrs sp;
        sp.p[0] = Wk; sp.p[1] = Wv; sp.p[2] = Wr; sp.p[3] = Wo; sp.p[4] = Wcr;
        sp.p[5] = Wck; sp.p[6] = Wcv;
        int grid = (int)((N4TOT + 255) / 256);
        cvtw_all<<<grid, 256>>>(sp, whb);
    }

    cudaFuncSetAttribute(gemm_fp16<0,0,0>, cudaFuncAttributeMaxDynamicSharedMemorySize, SMEM_BYTES);
    cudaFuncSetAttribute(gemm_fp16<1,0,0>, cudaFuncAttributeMaxDynamicSharedMemorySize, SMEM_BYTES);
    cudaFuncSetAttribute(gemm_fp16<2,0,1>, cudaFuncAttributeMaxDynamicSharedMemorySize, SMEM_BYTES);
    cudaFuncSetAttribute(gemm_fp16<0,1,0>, cudaFuncAttributeMaxDynamicSharedMemorySize, SMEM_BYTES);

    dim3 gC(C_ / BN, BT_ / BM);
    dim3 gF(F_ / BN, BT_ / BM);
    int elemGrid = (BT_ * C_) / 256;

    ln_kernel<<<BT_, 256>>>(x, ln0w, ln0b, xb);

    for (int l = 0; l < L_; l++) {
        size_t oC  = (size_t)l * C_;
        size_t oCC = (size_t)l * C_ * C_;
        size_t oFC = (size_t)l * F_ * C_;

        // ---- TimeMix ----
        ln_kernel<<<BT_, 256>>>(xb, ln1w + oC, ln1b + oC, h);
        mix3_kernel<<<elemGrid, 256>>>(h, tmk + oC, tmv + oC, tmr + oC, xk, xv, xr);
        gemm_fp16<0,0,0><<<gC, 256, SMEM_BYTES>>>(xk, tWk + oCC, kb,  nullptr, BT_, C_, C_);
        gemm_fp16<0,0,0><<<gC, 256, SMEM_BYTES>>>(xv, tWv + oCC, vb,  nullptr, BT_, C_, C_);
        gemm_fp16<1,0,0><<<gC, 256, SMEM_BYTES>>>(xr, tWr + oCC, srb, nullptr, BT_, C_, C_);
        wkv_pass1 <<<NBC / 256, 256>>>(kb, vb, td + oC, sLa, sLb, sLp);
        wkv_combine<<<(B_ * C_) / 256, 256>>>(sLa, sLb, sLp, pA, pB, pP, td + oC);
        wkv_pass2 <<<NBC / 256, 256>>>(kb, vb, srb, rwkvb, td + oC, tf + oC, pA, pB, pP);
        gemm_fp16<0,1,0><<<gC, 256, SMEM_BYTES>>>(rwkvb, tWo + oCC, xb, nullptr, BT_, C_, C_);

        // ---- ChannelMix ----
        ln_kernel<<<BT_, 256>>>(xb, ln2w + oC, ln2b + oC, h);
        mix2_kernel<<<elemGrid, 256>>>(h, cmk + oC, cmr + oC, xk, xr);
        gemm_fp16<2,0,1><<<gF, 256, SMEM_BYTES>>>(xk, tWck + oFC, kfb, nullptr, BT_, F_, C_);
        gemm_fp16<1,0,0><<<gC, 256, SMEM_BYTES>>>(xr, tWcr + oCC, srb, nullptr, BT_, C_, C_);
        gemm_fp16<0,1,0><<<gC, 256, SMEM_BYTES>>>(kfb, tWcv + oFC, xb, srb, BT_, C_, F_);
    }
}

// round 15
// speedup vs baseline: 1.5517x; 1.5517x over previous
#include <cuda_runtime.h>
#include <cuda_fp16.h>
#include <math.h>
#include <stdint.h>

#define L_ 4
#define B_ 4
#define T_ 2048
#define C_ 1024
#define F_ 4096
#define BT_ (B_*T_)
#define NCH 16
#define CHUNK (T_/NCH)     // 128
#define NBC (B_*NCH*C_)    // 65536

// ---------------- scratch (device globals: no allocations allowed) ----------
__device__ float  g_k   [BT_ * C_];
__device__ float  g_v   [BT_ * C_];
__device__ float  g_sr  [BT_ * C_];
__device__ float  g_cs  [6 * NBC];
__device__ __half g_xk  [BT_ * C_];
__device__ __half g_xv  [BT_ * C_];
__device__ __half g_xr  [BT_ * C_];
__device__ __half g_rwkv[BT_ * C_];
__device__ __half g_kf  [BT_ * F_];
#define WPL (5*C_*C_ + 2*C_*F_)
__device__ __half g_wh  [L_ * WPL];

// ---------------- weight pre-conversion to fp16 -----------------------------
__global__ __launch_bounds__(256) void cvtw_kernel(
    const float* __restrict__ src, __half* __restrict__ dst, size_t n4)
{
    size_t i = (size_t)blockIdx.x * 256 + threadIdx.x;
    if (i >= n4) return;
    float4 v = ((const float4*)src)[i];
    __half2 h01 = __floats2half2_rn(v.x, v.y);
    __half2 h23 = __floats2half2_rn(v.z, v.w);
    ((__half2*)dst)[2 * i]     = h01;
    ((__half2*)dst)[2 * i + 1] = h23;
}

// ---------------- plain layernorm (ln0 only) --------------------------------
__global__ __launch_bounds__(256) void ln_kernel(
    const float* __restrict__ x, const float* __restrict__ w,
    const float* __restrict__ b, float* __restrict__ y)
{
    int row = blockIdx.x;
    const float* xr = x + (size_t)row * C_;
    float*       yr = y + (size_t)row * C_;

    float s = 0.f, s2 = 0.f;
    for (int i = threadIdx.x; i < C_; i += 256) {
        float t = xr[i];
        s += t;
        s2 = fmaf(t, t, s2);
    }
    #pragma unroll
    for (int o = 16; o > 0; o >>= 1) {
        s  += __shfl_xor_sync(0xffffffffu, s,  o);
        s2 += __shfl_xor_sync(0xffffffffu, s2, o);
    }
    __shared__ float sh[2][8];
    int wid = threadIdx.x >> 5;
    if ((threadIdx.x & 31) == 0) { sh[0][wid] = s; sh[1][wid] = s2; }
    __syncthreads();
    if (threadIdx.x < 32) {
        float a  = (threadIdx.x < 8) ? sh[0][threadIdx.x] : 0.f;
        float c2 = (threadIdx.x < 8) ? sh[1][threadIdx.x] : 0.f;
        #pragma unroll
        for (int o = 4; o > 0; o >>= 1) {
            a  += __shfl_xor_sync(0xffffffffu, a,  o);
            c2 += __shfl_xor_sync(0xffffffffu, c2, o);
        }
        if (threadIdx.x == 0) { sh[0][0] = a; sh[1][0] = c2; }
    }
    __syncthreads();
    float mean = sh[0][0] * (1.f / C_);
    float var  = sh[1][0] * (1.f / C_) - mean * mean;
    float rstd = rsqrtf(var + 1e-5f);
    for (int i = threadIdx.x; i < C_; i += 256)
        yr[i] = (xr[i] - mean) * rstd * w[i] + b[i];
}

// ---------------- fused LN + time-shift mix ---------------------------------
// One block per row t: LN(x[t]) and LN(x[t-1]) computed in-block, mixed, fp16 out.
// NOUT = 3 (xk,xv,xr) or 2 (xk,xr).
template<int NOUT>
__global__ __launch_bounds__(256) void ln_mix_fused(
    const float* __restrict__ x, const float* __restrict__ w,
    const float* __restrict__ b,
    const float* __restrict__ mk, const float* __restrict__ mv,
    const float* __restrict__ mr,
    __half* __restrict__ xk, __half* __restrict__ xv, __half* __restrict__ xr)
{
    int row = blockIdx.x;
    int hasPrev = (row & (T_ - 1)) != 0;
    const float* xc = x + (size_t)row * C_;
    const float* xp = xc - C_;       // only read when hasPrev

    float s = 0.f, s2 = 0.f, ps = 0.f, ps2 = 0.f;
    for (int i = threadIdx.x; i < C_; i += 256) {
        float t = xc[i];
        s += t; s2 = fmaf(t, t, s2);
        if (hasPrev) {
            float u = xp[i];
            ps += u; ps2 = fmaf(u, u, ps2);
        }
    }
    #pragma unroll
    for (int o = 16; o > 0; o >>= 1) {
        s   += __shfl_xor_sync(0xffffffffu, s,   o);
        s2  += __shfl_xor_sync(0xffffffffu, s2,  o);
        ps  += __shfl_xor_sync(0xffffffffu, ps,  o);
        ps2 += __shfl_xor_sync(0xffffffffu, ps2, o);
    }
    __shared__ float sh[4][8];
    int wid = threadIdx.x >> 5;
    if ((threadIdx.x & 31) == 0) {
        sh[0][wid] = s; sh[1][wid] = s2; sh[2][wid] = ps; sh[3][wid] = ps2;
    }
    __syncthreads();
    if (threadIdx.x < 32) {
        float a0 = (threadIdx.x < 8) ? sh[0][threadIdx.x] : 0.f;
        float a1 = (threadIdx.x < 8) ? sh[1][threadIdx.x] : 0.f;
        float a2 = (threadIdx.x < 8) ? sh[2][threadIdx.x] : 0.f;
        float a3 = (threadIdx.x < 8) ? sh[3][threadIdx.x] : 0.f;
        #pragma unroll
        for (int o = 4; o > 0; o >>= 1) {
            a0 += __shfl_xor_sync(0xffffffffu, a0, o);
            a1 += __shfl_xor_sync(0xffffffffu, a1, o);
            a2 += __shfl_xor_sync(0xffffffffu, a2, o);
            a3 += __shfl_xor_sync(0xffffffffu, a3, o);
        }
        if (threadIdx.x == 0) { sh[0][0] = a0; sh[1][0] = a1; sh[2][0] = a2; sh[3][0] = a3; }
    }
    __syncthreads();
    float mean  = sh[0][0] * (1.f / C_);
    float var   = sh[1][0] * (1.f / C_) - mean * mean;
    float rstd  = rsqrtf(var + 1e-5f);
    float pmean = sh[2][0] * (1.f / C_);
    float pvar  = sh[3][0] * (1.f / C_) - pmean * pmean;
    float prstd = rsqrtf(pvar + 1e-5f);

    size_t base = (size_t)row * C_;
    for (int i = threadIdx.x; i < C_; i += 256) {
        float wi = w[i], bi = b[i];
        float ht = (xc[i] - mean) * rstd * wi + bi;
        float hp = hasPrev ? ((xp[i] - pmean) * prstd * wi + bi) : 0.f;
        float a = mk[i];
        xk[base + i] = __float2half(ht * a + hp * (1.f - a));
        if (NOUT == 3) {
            float bv = mv[i];
            xv[base + i] = __float2half(ht * bv + hp * (1.f - bv));
        }
        float rr = mr[i];
        xr[base + i] = __float2half(ht * rr + hp * (1.f - rr));
    }
}

// ---------------- WKV: chunked parallel scan --------------------------------
__global__ __launch_bounds__(256) void wkv_pass1(
    const float* __restrict__ k, const float* __restrict__ v,
    const float* __restrict__ td,
    float* __restrict__ sLa, float* __restrict__ sLb, float* __restrict__ sLp)
{
    int idx = blockIdx.x * 256 + threadIdx.x;
    int c  = idx & (C_ - 1);
    int ch = (idx >> 10) & (NCH - 1);
    int b  = idx >> 14;
    float w = -__expf(td[c]);
    float aa = 0.f, bb = 0.f, pp = -1e38f;
    size_t base = ((size_t)b * T_ + (size_t)ch * CHUNK) * C_ + c;
    #pragma unroll 4
    for (int i = 0; i < CHUNK; i++) {
        float kk = k[base + (size_t)i * C_];
        float vv = v[base + (size_t)i * C_];
        float ww2 = pp + w;
        float qq2 = fmaxf(ww2, kk);
        float e1 = __expf(ww2 - qq2);
        float e2 = __expf(kk  - qq2);
        aa = e1 * aa + e2 * vv;
        bb = e1 * bb + e2;
        pp = qq2;
    }
    sLa[idx] = aa; sLb[idx] = bb; sLp[idx] = pp;
}

__global__ __launch_bounds__(256) void wkv_combine(
    const float* __restrict__ sLa, const float* __restrict__ sLb,
    const float* __restrict__ sLp,
    float* __restrict__ pA, float* __restrict__ pB, float* __restrict__ pP,
    const float* __restrict__ td)
{
    int idx = blockIdx.x * 256 + threadIdx.x;
    int c = idx & (C_ - 1);
    int b = idx >> 10;
    float w  = -__expf(td[c]);
    float wc = w * (float)CHUNK;
    float aa = 0.f, bb = 0.f, pp = -1e38f;
    int base = b * NCH * C_ + c;
    #pragma unroll
    for (int ch = 0; ch < NCH; ch++) {
        int j = base + ch * C_;
        pA[j] = aa; pB[j] = bb; pP[j] = pp;
        float adv = pp + wc;
        float la = sLa[j], lb = sLb[j], lp = sLp[j];
        float q  = fmaxf(adv, lp);
        float e1 = __expf(adv - q);
        float e2 = __expf(lp  - q);
        aa = e1 * aa + e2 * la;
        bb = e1 * bb + e2 * lb;
        pp = q;
    }
}

__global__ __launch_bounds__(256) void wkv_pass2(
    const float* __restrict__ k, const float* __restrict__ v,
    const float* __restrict__ sr, __half* __restrict__ out,
    const float* __restrict__ td, const float* __restrict__ tf,
    const float* __restrict__ pA, const float* __restrict__ pB,
    const float* __restrict__ pP)
{
    int idx = blockIdx.x * 256 + threadIdx.x;
    int c  = idx & (C_ - 1);
    int ch = (idx >> 10) & (NCH - 1);
    int b  = idx >> 14;
    float w = -__expf(td[c]);
    float u = tf[c];
    float aa = pA[idx], bb = pB[idx], pp = pP[idx];
    size_t base = ((size_t)b * T_ + (size_t)ch * CHUNK) * C_ + c;
    #pragma unroll 4
    for (int i = 0; i < CHUNK; i++) {
        size_t off = base + (size_t)i * C_;
        float kk = k[off];
        float vv = v[off];
        float ww = u + kk;
        float qq = fmaxf(pp, ww);
        float e1 = __expf(pp - qq);
        float e2 = __expf(ww - qq);
        out[off] = __float2half(sr[off] * ((e1 * aa + e2 * vv) / (e1 * bb + e2)));
        float ww2 = pp + w;
        float qq2 = fmaxf(ww2, kk);
        float e1b = __expf(ww2 - qq2);
        float e2b = __expf(kk  - qq2);
        aa = e1b * aa + e2b * vv;
        bb = e1b * bb + e2b;
        pp = qq2;
    }
}

// ---------------- fp16 mma.sync GEMM: Y = X[M,K] . W[N,K]^T -----------------
// EXACT R12 configuration: 128x128 CTA tile, 8 warps (2x4, 64x32 warp tiles),
// BK=32, m16n8k16, scalar LDS fragments, 3-stage cp.async wait_group 1.
#define BM 128
#define BN 128
#define BK 32
#define SH 40                          // smem halves per row (conflict-free)
#define NSTAGE 3
#define STGH ((BM+BN)*SH)              // halves per stage
#define SMEM_BYTES (NSTAGE*STGH*2)

__device__ __forceinline__ void cp16(unsigned smaddr, const __half* g) {
    asm volatile("cp.async.cg.shared.global [%0], [%1], 16;" :: "r"(smaddr), "l"(g));
}

template<int EPI, int ACCUM, int OUTH>
__global__ __launch_bounds__(256, 2) void gemm_fp16(
    const __half* __restrict__ X, const __half* __restrict__ W,
    void* __restrict__ Yv, const float* __restrict__ mul,
    int M, int N, int K)
{
    extern __shared__ __half sm[];

    int tid  = threadIdx.x;
    int warp = tid >> 5, lane = tid & 31;
    int wm = warp >> 2, wn = warp & 3;          // 2 x 4 warp grid, 64x32 tiles
    int gid = lane >> 2, tig = lane & 3;

    const int bMr = blockIdx.y * BM, bNr = blockIdx.x * BN;
    int r  = tid >> 1;
    int c0 = tid & 1;                           // chunks c0 and c0+2 (of 4)
    const __half* GA = X + (size_t)(bMr + r) * K;
    const __half* GB = W + (size_t)(bNr + r) * K;
    unsigned sbase = (unsigned)__cvta_generic_to_shared(sm);
    unsigned rowA = (unsigned)(r * SH) * 2u;
    unsigned rowB = (unsigned)((BM + r) * SH) * 2u;

    float acc[4][4][4];
    #pragma unroll
    for (int i = 0; i < 4; i++)
        #pragma unroll
        for (int j = 0; j < 4; j++)
            #pragma unroll
            for (int q = 0; q < 4; q++) acc[i][j][q] = 0.f;

    int niter = K / BK;

    #pragma unroll
    for (int s = 0; s < NSTAGE - 1; s++) {
        unsigned dst = sbase + (unsigned)(s * STGH) * 2u;
        int k0 = s * BK;
        #pragma unroll
        for (int cc = 0; cc < 2; cc++) {
            int ch = c0 + cc * 2;
            cp16(dst + rowA + ch * 16u, GA + k0 + ch * 8);
            cp16(dst + rowB + ch * 16u, GB + k0 + ch * 8);
        }
        asm volatile("cp.async.commit_group;" ::: "memory");
    }

    for (int kt = 0; kt < niter; kt++) {
        asm volatile("cp.async.wait_group 1;" ::: "memory");
        __syncthreads();

        int nx = kt + NSTAGE - 1;
        if (nx < niter) {
            unsigned dst = sbase + (unsigned)((nx % NSTAGE) * STGH) * 2u;
            int k0 = nx * BK;
            #pragma unroll
            for (int cc = 0; cc < 2; cc++) {
                int ch = c0 + cc * 2;
                cp16(dst + rowA + ch * 16u, GA + k0 + ch * 8);
                cp16(dst + rowB + ch * 16u, GB + k0 + ch * 8);
            }
        }
        asm volatile("cp.async.commit_group;" ::: "memory");

        const __half* Ab = sm + (kt % NSTAGE) * STGH;
        const __half* Bb = Ab + BM * SH;

        #pragma unroll
        for (int kk = 0; kk < 2; kk++) {
            int k0 = kk * 16;
            unsigned af[4][4], bf[4][2];
            #pragma unroll
            for (int i = 0; i < 4; i++) {
                int rb = wm * 64 + i * 16 + gid;
                const __half* p0 = Ab + rb * SH + k0 + 2 * tig;
                const __half* p1 = Ab + (rb + 8) * SH + k0 + 2 * tig;
                af[i][0] = *(const unsigned*)(p0);
                af[i][1] = *(const unsigned*)(p1);
                af[i][2] = *(const unsigned*)(p0 + 8);
                af[i][3] = *(const unsigned*)(p1 + 8);
            }
            #pragma unroll
            for (int j = 0; j < 4; j++) {
                int nb = wn * 32 + j * 8 + gid;
                const __half* p = Bb + nb * SH + k0 + 2 * tig;
                bf[j][0] = *(const unsigned*)(p);
                bf[j][1] = *(const unsigned*)(p + 8);
            }
            #pragma unroll
            for (int i = 0; i < 4; i++)
                #pragma unroll
                for (int j = 0; j < 4; j++)
                    asm volatile(
                        "mma.sync.aligned.m16n8k16.row.col.f32.f16.f16.f32 "
                        "{%0,%1,%2,%3}, {%4,%5,%6,%7}, {%8,%9}, {%0,%1,%2,%3};"
                        : "+f"(acc[i][j][0]), "+f"(acc[i][j][1]),
                          "+f"(acc[i][j][2]), "+f"(acc[i][j][3])
                        : "r"(af[i][0]), "r"(af[i][1]), "r"(af[i][2]), "r"(af[i][3]),
                          "r"(bf[j][0]), "r"(bf[j][1]));
        }
    }

    float*  Yf = (float*)Yv;
    __half* Yh = (__half*)Yv;
    #pragma unroll
    for (int i = 0; i < 4; i++) {
        int rg = bMr + wm * 64 + i * 16 + gid;
        #pragma unroll
        for (int j = 0; j < 4; j++) {
            int cg = bNr + wn * 32 + j * 8 + tig * 2;
            #pragma unroll
            for (int h = 0; h < 2; h++) {
                int rr = rg + h * 8;
                #pragma unroll
                for (int q = 0; q < 2; q++) {
                    float v = acc[i][j][h * 2 + q];
                    if (EPI == 1) v = 1.f / (1.f + __expf(-v));
                    if (EPI == 2) { v = fmaxf(v, 0.f); v = v * v; }
                    size_t idx = (size_t)rr * N + (cg + q);
                    if (ACCUM) {
                        float m = mul ? mul[idx] : 1.f;
                        Yf[idx] += m * v;
                    } else if (OUTH) {
                        Yh[idx] = __float2half(v);
                    } else {
                        Yf[idx] = v;
                    }
                }
            }
        }
    }
}

// ---------------- host orchestration ----------------------------------------
extern "C" void kernel_launch(void* const* d_in, const int* in_sizes, int n_in,
                              void* d_out, int out_size)
{
    const float* x    = (const float*)d_in[0];
    const float* ln0w = (const float*)d_in[1];
    const float* ln0b = (const float*)d_in[2];
    const float* ln1w = (const float*)d_in[3];
    const float* ln1b = (const float*)d_in[4];
    const float* ln2w = (const float*)d_in[5];
    const float* ln2b = (const float*)d_in[6];
    const float* td   = (const float*)d_in[7];
    const float* tf   = (const float*)d_in[8];
    const float* tmk  = (const float*)d_in[9];
    const float* tmv  = (const float*)d_in[10];
    const float* tmr  = (const float*)d_in[11];
    const float* Wk   = (const float*)d_in[12];
    const float* Wv   = (const float*)d_in[13];
    const float* Wr   = (const float*)d_in[14];
    const float* Wo   = (const float*)d_in[15];
    const float* cmk  = (const float*)d_in[16];
    const float* cmr  = (const float*)d_in[17];
    const float* Wck  = (const float*)d_in[18];
    const float* Wcv  = (const float*)d_in[19];
    const float* Wcr  = (const float*)d_in[20];

    float* xb = (float*)d_out;

    float  *kb, *vb, *srb, *cs;
    __half *xk, *xv, *xr, *rwkvb, *kfb, *whb;
    cudaGetSymbolAddress((void**)&kb,    g_k);
    cudaGetSymbolAddress((void**)&vb,    g_v);
    cudaGetSymbolAddress((void**)&srb,   g_sr);
    cudaGetSymbolAddress((void**)&cs,    g_cs);
    cudaGetSymbolAddress((void**)&xk,    g_xk);
    cudaGetSymbolAddress((void**)&xv,    g_xv);
    cudaGetSymbolAddress((void**)&xr,    g_xr);
    cudaGetSymbolAddress((void**)&rwkvb, g_rwkv);
    cudaGetSymbolAddress((void**)&kfb,   g_kf);
    cudaGetSymbolAddress((void**)&whb,   g_wh);

    float* sLa = cs;
    float* sLb = cs + NBC;
    float* sLp = cs + 2 * NBC;
    float* pA  = cs + 3 * NBC;
    float* pB  = cs + 4 * NBC;
    float* pP  = cs + 5 * NBC;

    size_t nCC = (size_t)L_ * C_ * C_;
    size_t nFC = (size_t)L_ * F_ * C_;
    __half* tWk  = whb;
    __half* tWv  = tWk  + nCC;
    __half* tWr  = tWv  + nCC;
    __half* tWo  = tWr  + nCC;
    __half* tWcr = tWo  + nCC;
    __half* tWck = tWcr + nCC;
    __half* tWcv = tWck + nFC;

    {
        size_t q = nCC / 4;
        int grid = (int)((q + 255) / 256);
        cvtw_kernel<<<grid, 256>>>(Wk,  tWk,  q);
        cvtw_kernel<<<grid, 256>>>(Wv,  tWv,  q);
        cvtw_kernel<<<grid, 256>>>(Wr,  tWr,  q);
        cvtw_kernel<<<grid, 256>>>(Wo,  tWo,  q);
        cvtw_kernel<<<grid, 256>>>(Wcr, tWcr, q);
        size_t qf = nFC / 4;
        int gridf = (int)((qf + 255) / 256);
        cvtw_kernel<<<gridf, 256>>>(Wck, tWck, qf);
        cvtw_kernel<<<gridf, 256>>>(Wcv, tWcv, qf);
    }

    cudaFuncSetAttribute(gemm_fp16<0,0,0>, cudaFuncAttributeMaxDynamicSharedMemorySize, SMEM_BYTES);
    cudaFuncSetAttribute(gemm_fp16<1,0,0>, cudaFuncAttributeMaxDynamicSharedMemorySize, SMEM_BYTES);
    cudaFuncSetAttribute(gemm_fp16<2,0,1>, cudaFuncAttributeMaxDynamicSharedMemorySize, SMEM_BYTES);
    cudaFuncSetAttribute(gemm_fp16<0,1,0>, cudaFuncAttributeMaxDynamicSharedMemorySize, SMEM_BYTES);

    dim3 gC(C_ / BN, BT_ / BM);
    dim3 gF(F_ / BN, BT_ / BM);

    ln_kernel<<<BT_, 256>>>(x, ln0w, ln0b, xb);

    for (int l = 0; l < L_; l++) {
        size_t oC  = (size_t)l * C_;
        size_t oCC = (size_t)l * C_ * C_;
        size_t oFC = (size_t)l * F_ * C_;

        // ---- TimeMix ----
        ln_mix_fused<3><<<BT_, 256>>>(xb, ln1w + oC, ln1b + oC,
                                      tmk + oC, tmv + oC, tmr + oC, xk, xv, xr);
        gemm_fp16<0,0,0><<<gC, 256, SMEM_BYTES>>>(xk, tWk + oCC, kb,  nullptr, BT_, C_, C_);
        gemm_fp16<0,0,0><<<gC, 256, SMEM_BYTES>>>(xv, tWv + oCC, vb,  nullptr, BT_, C_, C_);
        gemm_fp16<1,0,0><<<gC, 256, SMEM_BYTES>>>(xr, tWr + oCC, srb, nullptr, BT_, C_, C_);
        wkv_pass1 <<<NBC / 256, 256>>>(kb, vb, td + oC, sLa, sLb, sLp);
        wkv_combine<<<(B_ * C_) / 256, 256>>>(sLa, sLb, sLp, pA, pB, pP, td + oC);
        wkv_pass2 <<<NBC / 256, 256>>>(kb, vb, srb, rwkvb, td + oC, tf + oC, pA, pB, pP);
        gemm_fp16<0,1,0><<<gC, 256, SMEM_BYTES>>>(rwkvb, tWo + oCC, xb, nullptr, BT_, C_, C_);

        // ---- ChannelMix ----
        ln_mix_fused<2><<<BT_, 256>>>(xb, ln2w + oC, ln2b + oC,
                                      cmk + oC, nullptr, cmr + oC, xk, nullptr, xr);
        gemm_fp16<2,0,1><<<gF, 256, SMEM_BYTES>>>(xk, tWck + oFC, kfb, nullptr, BT_, F_, C_);
        gemm_fp16<1,0,0><<<gC, 256, SMEM_BYTES>>>(xr, tWcr + oCC, srb, nullptr, BT_, C_, C_);
        gemm_fp16<0,1,0><<<gC, 256, SMEM_BYTES>>>(kfb, tWcv + oFC, xb, srb, BT_, C_, F_);
    }
}

// round 17
// speedup vs baseline: 1.5592x; 1.0048x over previous
#include <cuda_runtime.h>
#include <cuda_fp16.h>
#include <math.h>
#include <stdint.h>

#define L_ 4
#define B_ 4
#define T_ 2048
#define C_ 1024
#define F_ 4096
#define BT_ (B_*T_)
#define NCH 16
#define CHUNK (T_/NCH)     // 128
#define NBC (B_*NCH*C_)    // 65536

// ---------------- scratch (device globals: no allocations allowed) ----------
__device__ float  g_cs  [6 * NBC];
__device__ __half g_k   [BT_ * C_];
__device__ __half g_v   [BT_ * C_];
__device__ __half g_sr  [BT_ * C_];
__device__ __half g_xk  [BT_ * C_];
__device__ __half g_xv  [BT_ * C_];
__device__ __half g_xr  [BT_ * C_];
__device__ __half g_rwkv[BT_ * C_];
__device__ __half g_kf  [BT_ * F_];
#define WPL (5*C_*C_ + 2*C_*F_)
__device__ __half g_wh  [L_ * WPL];

// ---------------- weight pre-conversion to fp16 -----------------------------
__global__ __launch_bounds__(256) void cvtw_kernel(
    const float* __restrict__ src, __half* __restrict__ dst, size_t n4)
{
    size_t i = (size_t)blockIdx.x * 256 + threadIdx.x;
    if (i >= n4) return;
    float4 v = ((const float4*)src)[i];
    __half2 h01 = __floats2half2_rn(v.x, v.y);
    __half2 h23 = __floats2half2_rn(v.z, v.w);
    ((__half2*)dst)[2 * i]     = h01;
    ((__half2*)dst)[2 * i + 1] = h23;
}

// ---------------- plain layernorm (ln0 only) --------------------------------
__global__ __launch_bounds__(256) void ln_kernel(
    const float* __restrict__ x, const float* __restrict__ w,
    const float* __restrict__ b, float* __restrict__ y)
{
    int row = blockIdx.x;
    const float* xr = x + (size_t)row * C_;
    float*       yr = y + (size_t)row * C_;

    float s = 0.f, s2 = 0.f;
    for (int i = threadIdx.x; i < C_; i += 256) {
        float t = xr[i];
        s += t;
        s2 = fmaf(t, t, s2);
    }
    #pragma unroll
    for (int o = 16; o > 0; o >>= 1) {
        s  += __shfl_xor_sync(0xffffffffu, s,  o);
        s2 += __shfl_xor_sync(0xffffffffu, s2, o);
    }
    __shared__ float sh[2][8];
    int wid = threadIdx.x >> 5;
    if ((threadIdx.x & 31) == 0) { sh[0][wid] = s; sh[1][wid] = s2; }
    __syncthreads();
    if (threadIdx.x < 32) {
        float a  = (threadIdx.x < 8) ? sh[0][threadIdx.x] : 0.f;
        float c2 = (threadIdx.x < 8) ? sh[1][threadIdx.x] : 0.f;
        #pragma unroll
        for (int o = 4; o > 0; o >>= 1) {
            a  += __shfl_xor_sync(0xffffffffu, a,  o);
            c2 += __shfl_xor_sync(0xffffffffu, c2, o);
        }
        if (threadIdx.x == 0) { sh[0][0] = a; sh[1][0] = c2; }
    }
    __syncthreads();
    float mean = sh[0][0] * (1.f / C_);
    float var  = sh[1][0] * (1.f / C_) - mean * mean;
    float rstd = rsqrtf(var + 1e-5f);
    for (int i = threadIdx.x; i < C_; i += 256)
        yr[i] = (xr[i] - mean) * rstd * w[i] + b[i];
}

// ---------------- fused LN + time-shift mix ---------------------------------
template<int NOUT>
__global__ __launch_bounds__(256) void ln_mix_fused(
    const float* __restrict__ x, const float* __restrict__ w,
    const float* __restrict__ b,
    const float* __restrict__ mk, const float* __restrict__ mv,
    const float* __restrict__ mr,
    __half* __restrict__ xk, __half* __restrict__ xv, __half* __restrict__ xr)
{
    int row = blockIdx.x;
    int hasPrev = (row & (T_ - 1)) != 0;
    const float* xc = x + (size_t)row * C_;
    const float* xp = xc - C_;

    float s = 0.f, s2 = 0.f, ps = 0.f, ps2 = 0.f;
    for (int i = threadIdx.x; i < C_; i += 256) {
        float t = xc[i];
        s += t; s2 = fmaf(t, t, s2);
        if (hasPrev) {
            float u = xp[i];
            ps += u; ps2 = fmaf(u, u, ps2);
        }
    }
    #pragma unroll
    for (int o = 16; o > 0; o >>= 1) {
        s   += __shfl_xor_sync(0xffffffffu, s,   o);
        s2  += __shfl_xor_sync(0xffffffffu, s2,  o);
        ps  += __shfl_xor_sync(0xffffffffu, ps,  o);
        ps2 += __shfl_xor_sync(0xffffffffu, ps2, o);
    }
    __shared__ float sh[4][8];
    int wid = threadIdx.x >> 5;
    if ((threadIdx.x & 31) == 0) {
        sh[0][wid] = s; sh[1][wid] = s2; sh[2][wid] = ps; sh[3][wid] = ps2;
    }
    __syncthreads();
    if (threadIdx.x < 32) {
        float a0 = (threadIdx.x < 8) ? sh[0][threadIdx.x] : 0.f;
        float a1 = (threadIdx.x < 8) ? sh[1][threadIdx.x] : 0.f;
        float a2 = (threadIdx.x < 8) ? sh[2][threadIdx.x] : 0.f;
        float a3 = (threadIdx.x < 8) ? sh[3][threadIdx.x] : 0.f;
        #pragma unroll
        for (int o = 4; o > 0; o >>= 1) {
            a0 += __shfl_xor_sync(0xffffffffu, a0, o);
            a1 += __shfl_xor_sync(0xffffffffu, a1, o);
            a2 += __shfl_xor_sync(0xffffffffu, a2, o);
            a3 += __shfl_xor_sync(0xffffffffu, a3, o);
        }
        if (threadIdx.x == 0) { sh[0][0] = a0; sh[1][0] = a1; sh[2][0] = a2; sh[3][0] = a3; }
    }
    __syncthreads();
    float mean  = sh[0][0] * (1.f / C_);
    float var   = sh[1][0] * (1.f / C_) - mean * mean;
    float rstd  = rsqrtf(var + 1e-5f);
    float pmean = sh[2][0] * (1.f / C_);
    float pvar  = sh[3][0] * (1.f / C_) - pmean * pmean;
    float prstd = rsqrtf(pvar + 1e-5f);

    size_t base = (size_t)row * C_;
    for (int i = threadIdx.x; i < C_; i += 256) {
        float wi = w[i], bi = b[i];
        float ht = (xc[i] - mean) * rstd * wi + bi;
        float hp = hasPrev ? ((xp[i] - pmean) * prstd * wi + bi) : 0.f;
        float a = mk[i];
        xk[base + i] = __float2half(ht * a + hp * (1.f - a));
        if (NOUT == 3) {
            float bv = mv[i];
            xv[base + i] = __float2half(ht * bv + hp * (1.f - bv));
        }
        float rr = mr[i];
        xr[base + i] = __float2half(ht * rr + hp * (1.f - rr));
    }
}

// ---------------- WKV: chunked parallel scan (fp16 k/v/sr) ------------------
__global__ __launch_bounds__(256) void wkv_pass1(
    const __half* __restrict__ k, const __half* __restrict__ v,
    const float* __restrict__ td,
    float* __restrict__ sLa, float* __restrict__ sLb, float* __restrict__ sLp)
{
    int idx = blockIdx.x * 256 + threadIdx.x;
    int c  = idx & (C_ - 1);
    int ch = (idx >> 10) & (NCH - 1);
    int b  = idx >> 14;
    float w = -__expf(td[c]);
    float aa = 0.f, bb = 0.f, pp = -1e38f;
    size_t base = ((size_t)b * T_ + (size_t)ch * CHUNK) * C_ + c;
    #pragma unroll 4
    for (int i = 0; i < CHUNK; i++) {
        float kk = __half2float(k[base + (size_t)i * C_]);
        float vv = __half2float(v[base + (size_t)i * C_]);
        float ww2 = pp + w;
        float qq2 = fmaxf(ww2, kk);
        float e1 = __expf(ww2 - qq2);
        float e2 = __expf(kk  - qq2);
        aa = e1 * aa + e2 * vv;
        bb = e1 * bb + e2;
        pp = qq2;
    }
    sLa[idx] = aa; sLb[idx] = bb; sLp[idx] = pp;
}

__global__ __launch_bounds__(256) void wkv_combine(
    const float* __restrict__ sLa, const float* __restrict__ sLb,
    const float* __restrict__ sLp,
    float* __restrict__ pA, float* __restrict__ pB, float* __restrict__ pP,
    const float* __restrict__ td)
{
    int idx = blockIdx.x * 256 + threadIdx.x;
    int c = idx & (C_ - 1);
    int b = idx >> 10;
    float w  = -__expf(td[c]);
    float wc = w * (float)CHUNK;
    float aa = 0.f, bb = 0.f, pp = -1e38f;
    int base = b * NCH * C_ + c;
    #pragma unroll
    for (int ch = 0; ch < NCH; ch++) {
        int j = base + ch * C_;
        pA[j] = aa; pB[j] = bb; pP[j] = pp;
        float adv = pp + wc;
        float la = sLa[j], lb = sLb[j], lp = sLp[j];
        float q  = fmaxf(adv, lp);
        float e1 = __expf(adv - q);
        float e2 = __expf(lp  - q);
        aa = e1 * aa + e2 * la;
        bb = e1 * bb + e2 * lb;
        pp = q;
    }
}

__global__ __launch_bounds__(256) void wkv_pass2(
    const __half* __restrict__ k, const __half* __restrict__ v,
    const __half* __restrict__ sr, __half* __restrict__ out,
    const float* __restrict__ td, const float* __restrict__ tf,
    const float* __restrict__ pA, const float* __restrict__ pB,
    const float* __restrict__ pP)
{
    int idx = blockIdx.x * 256 + threadIdx.x;
    int c  = idx & (C_ - 1);
    int ch = (idx >> 10) & (NCH - 1);
    int b  = idx >> 14;
    float w = -__expf(td[c]);
    float u = tf[c];
    float aa = pA[idx], bb = pB[idx], pp = pP[idx];
    size_t base = ((size_t)b * T_ + (size_t)ch * CHUNK) * C_ + c;
    #pragma unroll 4
    for (int i = 0; i < CHUNK; i++) {
        size_t off = base + (size_t)i * C_;
        float kk = __half2float(k[off]);
        float vv = __half2float(v[off]);
        float ww = u + kk;
        float qq = fmaxf(pp, ww);
        float e1 = __expf(pp - qq);
        float e2 = __expf(ww - qq);
        out[off] = __float2half(__half2float(sr[off]) *
                                ((e1 * aa + e2 * vv) / (e1 * bb + e2)));
        float ww2 = pp + w;
        float qq2 = fmaxf(ww2, kk);
        float e1b = __expf(ww2 - qq2);
        float e2b = __expf(kk  - qq2);
        aa = e1b * aa + e2b * vv;
        bb = e1b * bb + e2b;
        pp = qq2;
    }
}

// ---------------- fp16 mma.sync GEMM: Y = X[M,K] . W[N,K]^T -----------------
// EXACT R12/R15 mainloop: 128x128 CTA tile, 8 warps (2x4, 64x32 warp tiles),
// BK=32, m16n8k16, scalar LDS fragments, 3-stage cp.async wait_group 1.
#define BM 128
#define BN 128
#define BK 32
#define SH 40
#define NSTAGE 3
#define STGH ((BM+BN)*SH)
#define SMEM_BYTES (NSTAGE*STGH*2)

__device__ __forceinline__ void cp16(unsigned smaddr, const __half* g) {
    asm volatile("cp.async.cg.shared.global [%0], [%1], 16;" :: "r"(smaddr), "l"(g));
}

template<int EPI, int ACCUM, int OUTH>
__global__ __launch_bounds__(256, 2) void gemm_fp16(
    const __half* __restrict__ X, const __half* __restrict__ W,
    void* __restrict__ Yv, const __half* __restrict__ mul,
    int M, int N, int K)
{
    extern __shared__ __half sm[];

    int tid  = threadIdx.x;
    int warp = tid >> 5, lane = tid & 31;
    int wm = warp >> 2, wn = warp & 3;
    int gid = lane >> 2, tig = lane & 3;

    const int bMr = blockIdx.y * BM, bNr = blockIdx.x * BN;
    int r  = tid >> 1;
    int c0 = tid & 1;
    const __half* GA = X + (size_t)(bMr + r) * K;
    const __half* GB = W + (size_t)(bNr + r) * K;
    unsigned sbase = (unsigned)__cvta_generic_to_shared(sm);
    unsigned rowA = (unsigned)(r * SH) * 2u;
    unsigned rowB = (unsigned)((BM + r) * SH) * 2u;

    float acc[4][4][4];
    #pragma unroll
    for (int i = 0; i < 4; i++)
        #pragma unroll
        for (int j = 0; j < 4; j++)
            #pragma unroll
            for (int q = 0; q < 4; q++) acc[i][j][q] = 0.f;

    int niter = K / BK;

    #pragma unroll
    for (int s = 0; s < NSTAGE - 1; s++) {
        unsigned dst = sbase + (unsigned)(s * STGH) * 2u;
        int k0 = s * BK;
        #pragma unroll
        for (int cc = 0; cc < 2; cc++) {
            int ch = c0 + cc * 2;
            cp16(dst + rowA + ch * 16u, GA + k0 + ch * 8);
            cp16(dst + rowB + ch * 16u, GB + k0 + ch * 8);
        }
        asm volatile("cp.async.commit_group;" ::: "memory");
    }

    for (int kt = 0; kt < niter; kt++) {
        asm volatile("cp.async.wait_group 1;" ::: "memory");
        __syncthreads();

        int nx = kt + NSTAGE - 1;
        if (nx < niter) {
            unsigned dst = sbase + (unsigned)((nx % NSTAGE) * STGH) * 2u;
            int k0 = nx * BK;
            #pragma unroll
            for (int cc = 0; cc < 2; cc++) {
                int ch = c0 + cc * 2;
                cp16(dst + rowA + ch * 16u, GA + k0 + ch * 8);
                cp16(dst + rowB + ch * 16u, GB + k0 + ch * 8);
            }
        }
        asm volatile("cp.async.commit_group;" ::: "memory");

        const __half* Ab = sm + (kt % NSTAGE) * STGH;
        const __half* Bb = Ab + BM * SH;

        #pragma unroll
        for (int kk = 0; kk < 2; kk++) {
            int k0 = kk * 16;
            unsigned af[4][4], bf[4][2];
            #pragma unroll
            for (int i = 0; i < 4; i++) {
                int rb = wm * 64 + i * 16 + gid;
                const __half* p0 = Ab + rb * SH + k0 + 2 * tig;
                const __half* p1 = Ab + (rb + 8) * SH + k0 + 2 * tig;
                af[i][0] = *(const unsigned*)(p0);
                af[i][1] = *(const unsigned*)(p1);
                af[i][2] = *(const unsigned*)(p0 + 8);
                af[i][3] = *(const unsigned*)(p1 + 8);
            }
            #pragma unroll
            for (int j = 0; j < 4; j++) {
                int nb = wn * 32 + j * 8 + gid;
                const __half* p = Bb + nb * SH + k0 + 2 * tig;
                bf[j][0] = *(const unsigned*)(p);
                bf[j][1] = *(const unsigned*)(p + 8);
            }
            #pragma unroll
            for (int i = 0; i < 4; i++)
                #pragma unroll
                for (int j = 0; j < 4; j++)
                    asm volatile(
                        "mma.sync.aligned.m16n8k16.row.col.f32.f16.f16.f32 "
                        "{%0,%1,%2,%3}, {%4,%5,%6,%7}, {%8,%9}, {%0,%1,%2,%3};"
                        : "+f"(acc[i][j][0]), "+f"(acc[i][j][1]),
                          "+f"(acc[i][j][2]), "+f"(acc[i][j][3])
                        : "r"(af[i][0]), "r"(af[i][1]), "r"(af[i][2]), "r"(af[i][3]),
                          "r"(bf[j][0]), "r"(bf[j][1]));
        }
    }

    float*  Yf = (float*)Yv;
    __half* Yh = (__half*)Yv;
    #pragma unroll
    for (int i = 0; i < 4; i++) {
        int rg = bMr + wm * 64 + i * 16 + gid;
        #pragma unroll
        for (int j = 0; j < 4; j++) {
            int cg = bNr + wn * 32 + j * 8 + tig * 2;
            #pragma unroll
            for (int h = 0; h < 2; h++) {
                int rr = rg + h * 8;
                #pragma unroll
                for (int q = 0; q < 2; q++) {
                    float v = acc[i][j][h * 2 + q];
                    if (EPI == 1) v = 1.f / (1.f + __expf(-v));
                    if (EPI == 2) { v = fmaxf(v, 0.f); v = v * v; }
                    size_t idx = (size_t)rr * N + (cg + q);
                    if (ACCUM) {
                        float m = mul ? __half2float(mul[idx]) : 1.f;
                        Yf[idx] += m * v;
                    } else if (OUTH) {
                        Yh[idx] = __float2half(v);
                    } else {
                        Yf[idx] = v;
                    }
                }
            }
        }
    }
}

// ---------------- host orchestration ----------------------------------------
extern "C" void kernel_launch(void* const* d_in, const int* in_sizes, int n_in,
                              void* d_out, int out_size)
{
    const float* x    = (const float*)d_in[0];
    const float* ln0w = (const float*)d_in[1];
    const float* ln0b = (const float*)d_in[2];
    const float* ln1w = (const float*)d_in[3];
    const float* ln1b = (const float*)d_in[4];
    const float* ln2w = (const float*)d_in[5];
    const float* ln2b = (const float*)d_in[6];
    const float* td   = (const float*)d_in[7];
    const float* tf   = (const float*)d_in[8];
    const float* tmk  = (const float*)d_in[9];
    const float* tmv  = (const float*)d_in[10];
    const float* tmr  = (const float*)d_in[11];
    const float* Wk   = (const float*)d_in[12];
    const float* Wv   = (const float*)d_in[13];
    const float* Wr   = (const float*)d_in[14];
    const float* Wo   = (const float*)d_in[15];
    const float* cmk  = (const float*)d_in[16];
    const float* cmr  = (const float*)d_in[17];
    const float* Wck  = (const float*)d_in[18];
    const float* Wcv  = (const float*)d_in[19];
    const float* Wcr  = (const float*)d_in[20];

    float* xb = (float*)d_out;

    float  *cs;
    __half *kb, *vb, *srb, *xk, *xv, *xr, *rwkvb, *kfb, *whb;
    cudaGetSymbolAddress((void**)&cs,    g_cs);
    cudaGetSymbolAddress((void**)&kb,    g_k);
    cudaGetSymbolAddress((void**)&vb,    g_v);
    cudaGetSymbolAddress((void**)&srb,   g_sr);
    cudaGetSymbolAddress((void**)&xk,    g_xk);
    cudaGetSymbolAddress((void**)&xv,    g_xv);
    cudaGetSymbolAddress((void**)&xr,    g_xr);
    cudaGetSymbolAddress((void**)&rwkvb, g_rwkv);
    cudaGetSymbolAddress((void**)&kfb,   g_kf);
    cudaGetSymbolAddress((void**)&whb,   g_wh);

    float* sLa = cs;
    float* sLb = cs + NBC;
    float* sLp = cs + 2 * NBC;
    float* pA  = cs + 3 * NBC;
    float* pB  = cs + 4 * NBC;
    float* pP  = cs + 5 * NBC;

    size_t nCC = (size_t)L_ * C_ * C_;
    size_t nFC = (size_t)L_ * F_ * C_;
    __half* tWk  = whb;
    __half* tWv  = tWk  + nCC;
    __half* tWr  = tWv  + nCC;
    __half* tWo  = tWr  + nCC;
    __half* tWcr = tWo  + nCC;
    __half* tWck = tWcr + nCC;
    __half* tWcv = tWck + nFC;

    {
        size_t q = nCC / 4;
        int grid = (int)((q + 255) / 256);
        cvtw_kernel<<<grid, 256>>>(Wk,  tWk,  q);
        cvtw_kernel<<<grid, 256>>>(Wv,  tWv,  q);
        cvtw_kernel<<<grid, 256>>>(Wr,  tWr,  q);
        cvtw_kernel<<<grid, 256>>>(Wo,  tWo,  q);
        cvtw_kernel<<<grid, 256>>>(Wcr, tWcr, q);
        size_t qf = nFC / 4;
        int gridf = (int)((qf + 255) / 256);
        cvtw_kernel<<<gridf, 256>>>(Wck, tWck, qf);
        cvtw_kernel<<<gridf, 256>>>(Wcv, tWcv, qf);
    }

    cudaFuncSetAttribute(gemm_fp16<0,0,1>, cudaFuncAttributeMaxDynamicSharedMemorySize, SMEM_BYTES);
    cudaFuncSetAttribute(gemm_fp16<1,0,1>, cudaFuncAttributeMaxDynamicSharedMemorySize, SMEM_BYTES);
    cudaFuncSetAttribute(gemm_fp16<2,0,1>, cudaFuncAttributeMaxDynamicSharedMemorySize, SMEM_BYTES);
    cudaFuncSetAttribute(gemm_fp16<0,1,0>, cudaFuncAttributeMaxDynamicSharedMemorySize, SMEM_BYTES);

    dim3 gC(C_ / BN, BT_ / BM);
    dim3 gF(F_ / BN, BT_ / BM);

    ln_kernel<<<BT_, 256>>>(x, ln0w, ln0b, xb);

    for (int l = 0; l < L_; l++) {
        size_t oC  = (size_t)l * C_;
        size_t oCC = (size_t)l * C_ * C_;
        size_t oFC = (size_t)l * F_ * C_;

        // ---- TimeMix ----
        ln_mix_fused<3><<<BT_, 256>>>(xb, ln1w + oC, ln1b + oC,
                                      tmk + oC, tmv + oC, tmr + oC, xk, xv, xr);
        gemm_fp16<0,0,1><<<gC, 256, SMEM_BYTES>>>(xk, tWk + oCC, kb,  nullptr, BT_, C_, C_);
        gemm_fp16<0,0,1><<<gC, 256, SMEM_BYTES>>>(xv, tWv + oCC, vb,  nullptr, BT_, C_, C_);
        gemm_fp16<1,0,1><<<gC, 256, SMEM_BYTES>>>(xr, tWr + oCC, srb, nullptr, BT_, C_, C_);
        wkv_pass1 <<<NBC / 256, 256>>>(kb, vb, td + oC, sLa, sLb, sLp);
        wkv_combine<<<(B_ * C_) / 256, 256>>>(sLa, sLb, sLp, pA, pB, pP, td + oC);
        wkv_pass2 <<<NBC / 256, 256>>>(kb, vb, srb, rwkvb, td + oC, tf + oC, pA, pB, pP);
        gemm_fp16<0,1,0><<<gC, 256, SMEM_BYTES>>>(rwkvb, tWo + oCC, xb, nullptr, BT_, C_, C_);

        // ---- ChannelMix ----
        ln_mix_fused<2><<<BT_, 256>>>(xb, ln2w + oC, ln2b + oC,
                                      cmk + oC, nullptr, cmr + oC, xk, nullptr, xr);
        gemm_fp16<2,0,1><<<gF, 256, SMEM_BYTES>>>(xk, tWck + oFC, kfb, nullptr, BT_, F_, C_);
        gemm_fp16<1,0,1><<<gC, 256, SMEM_BYTES>>>(xr, tWcr + oCC, srb, nullptr, BT_, C_, C_);
        gemm_fp16<0,1,0><<<gC, 256, SMEM_BYTES>>>(kfb, tWcv + oFC, xb, srb, BT_, C_, F_);
    }
}